// round 1
// baseline (speedup 1.0000x reference)
#include <cuda_runtime.h>
#include <cstdint>
#include <math.h>

// Problem constants (fixed shapes from reference)
#define B_N   16384
#define K_N   50
#define D_N   64
#define R_N   8
#define V_N   100000
#define BK_N  (B_N * K_N)          // 819200

// ---------------------------------------------------------------------------
// Device scratch (static allocation — no cudaMalloc allowed)
// ---------------------------------------------------------------------------
__device__ float g_P  [(size_t)V_N * D_N];     // u2e @ w1_W[0:64,:]   25.6 MB
__device__ float g_A1B[(size_t)V_N * D_N];     // u2e @ a1_W[64:128,:] 25.6 MB
__device__ float g_O  [(size_t)BK_N * D_N];    // o_history            209.7 MB
__device__ float g_S  [(size_t)BK_N];          // attention scores     3.3 MB

// ---------------------------------------------------------------------------
// Kernel 0: per-vocab precompute of P and A1B.
//   P[v][j]   = sum_i u2e[v][i] * w1_W[i][j]
//   A1B[v][j] = sum_i u2e[v][i] * a1_W[64+i][j]
// Block = 256 threads = 4 vocab rows x 64 outputs. Weights cached in shared.
// ---------------------------------------------------------------------------
__global__ void __launch_bounds__(256) k_pre(const float* __restrict__ u2e,
                                             const float* __restrict__ w1W,
                                             const float* __restrict__ a1W)
{
    __shared__ float sW1[64 * 64];
    __shared__ float sA1[64 * 64];
    __shared__ float su[256];

    const int tid = threadIdx.x;
    for (int t = tid; t < 4096; t += 256) {
        sW1[t] = w1W[t];            // rows 0..63 of w1_W
        sA1[t] = a1W[4096 + t];     // rows 64..127 of a1_W
    }
    __syncthreads();

    const int vsub = tid >> 6;       // 0..3
    const int j    = tid & 63;

    for (int vb = blockIdx.x * 4; vb < V_N; vb += gridDim.x * 4) {
        su[tid] = u2e[(size_t)vb * 64 + tid];   // 4 rows of u2e
        __syncthreads();

        const float* u = su + (vsub << 6);
        float ap = 0.f, aa = 0.f;
        #pragma unroll
        for (int i = 0; i < 64; i++) {
            const float ui = u[i];
            ap = fmaf(ui, sW1[(i << 6) + j], ap);
            aa = fmaf(ui, sA1[(i << 6) + j], aa);
        }
        const size_t v = (size_t)(vb + vsub);
        g_P  [v * 64 + j] = ap;
        g_A1B[v * 64 + j] = aa;
        __syncthreads();   // protect su before next iteration overwrites
    }
}

// ---------------------------------------------------------------------------
// Kernel 1: per-(b,k)-pair fused MLP chain. Thread-per-pair, grid-stride.
// Weights live in shared (broadcast reads). Activations in registers.
// Writes o -> g_O, score -> g_S.
// ---------------------------------------------------------------------------
#define SMEM_FLOATS 13120   // 3*4096 + 512 + 5*64
#define SMEM_BYTES  (SMEM_FLOATS * 4)

__global__ void __launch_bounds__(128, 2) k_pairs(
    const int*   __restrict__ nodes,
    const int*   __restrict__ nidx,
    const float* __restrict__ labels,
    const float* __restrict__ w1W,
    const float* __restrict__ w1b,
    const float* __restrict__ w2W,
    const float* __restrict__ w2b,
    const float* __restrict__ a1W,
    const float* __restrict__ a1b,
    const float* __restrict__ a2W,
    const float* __restrict__ a2b,
    const float* __restrict__ a3W,
    const float* __restrict__ a3b)
{
    extern __shared__ float smem[];
    float* sW2  = smem;             // 4096
    float* sA1  = smem + 4096;      // 4096  (rows 0..63 of a1_W)
    float* sA2  = smem + 8192;      // 4096
    float* sW1L = smem + 12288;     // 512   (rows 64..71 of w1_W — labels part)
    float* sB1  = smem + 12800;     // 64
    float* sB2  = smem + 12864;     // 64
    float* sBa1 = smem + 12928;     // 64
    float* sBa2 = smem + 12992;     // 64
    float* sA3  = smem + 13056;     // 64

    const int tid = threadIdx.x;
    for (int t = tid; t < 4096; t += 128) {
        sW2[t] = w2W[t];
        sA1[t] = a1W[t];
        sA2[t] = a2W[t];
    }
    for (int t = tid; t < 512; t += 128) sW1L[t] = w1W[4096 + t];
    if (tid < 64) {
        sB1 [tid] = w1b[tid];
        sB2 [tid] = w2b[tid];
        sBa1[tid] = a1b[tid];
        sBa2[tid] = a2b[tid];
        sA3 [tid] = a3W[tid];
    }
    __syncthreads();

    const float a3b0 = a3b[0];

    for (int p = blockIdx.x * 128 + tid; p < BK_N; p += gridDim.x * 128) {
        const int b    = p / K_N;
        const int node = nodes[b];
        const int ni   = nidx[p];

        float x[64];

        // ---- Layer 1: h = relu(P[ni] + labels @ W1L + b1) ----
        {
            const float4* lv = reinterpret_cast<const float4*>(labels + (size_t)p * 8);
            const float4 la = lv[0], lb = lv[1];
            const float lab[8] = { la.x, la.y, la.z, la.w, lb.x, lb.y, lb.z, lb.w };

            const float4* Pv  = reinterpret_cast<const float4*>(g_P + (size_t)ni * 64);
            const float4* B1v = reinterpret_cast<const float4*>(sB1);
            const float4* W1v = reinterpret_cast<const float4*>(sW1L);
            #pragma unroll
            for (int j4 = 0; j4 < 16; j4++) {
                float4 a = Pv[j4];
                const float4 bb = B1v[j4];
                a.x += bb.x; a.y += bb.y; a.z += bb.z; a.w += bb.w;
                #pragma unroll
                for (int r = 0; r < 8; r++) {
                    const float4 w = W1v[r * 16 + j4];
                    a.x = fmaf(lab[r], w.x, a.x);
                    a.y = fmaf(lab[r], w.y, a.y);
                    a.z = fmaf(lab[r], w.z, a.z);
                    a.w = fmaf(lab[r], w.w, a.w);
                }
                x[4*j4+0] = fmaxf(a.x, 0.f);
                x[4*j4+1] = fmaxf(a.y, 0.f);
                x[4*j4+2] = fmaxf(a.z, 0.f);
                x[4*j4+3] = fmaxf(a.w, 0.f);
            }
        }

        // ---- Layers 2..4: x <- relu(x @ W + bias(+A1B gather on L==1)) ----
        #pragma unroll 1
        for (int L = 0; L < 3; L++) {
            const float4* Wv;
            const float4* bv;
            if (L == 0)      { Wv = (const float4*)sW2; bv = (const float4*)sB2;  }
            else if (L == 1) { Wv = (const float4*)sA1; bv = (const float4*)sBa1; }
            else             { Wv = (const float4*)sA2; bv = (const float4*)sBa2; }

            float acc[64];
            if (L == 1) {
                const float4* Gv = reinterpret_cast<const float4*>(g_A1B + (size_t)node * 64);
                #pragma unroll
                for (int j4 = 0; j4 < 16; j4++) {
                    const float4 bb = bv[j4];
                    const float4 g  = Gv[j4];
                    acc[4*j4+0] = bb.x + g.x;
                    acc[4*j4+1] = bb.y + g.y;
                    acc[4*j4+2] = bb.z + g.z;
                    acc[4*j4+3] = bb.w + g.w;
                }
            } else {
                #pragma unroll
                for (int j4 = 0; j4 < 16; j4++) {
                    const float4 bb = bv[j4];
                    acc[4*j4+0] = bb.x;
                    acc[4*j4+1] = bb.y;
                    acc[4*j4+2] = bb.z;
                    acc[4*j4+3] = bb.w;
                }
            }

            #pragma unroll
            for (int i = 0; i < 64; i++) {
                const float xi = x[i];
                #pragma unroll
                for (int j4 = 0; j4 < 16; j4++) {
                    const float4 w = Wv[i * 16 + j4];
                    acc[4*j4+0] = fmaf(xi, w.x, acc[4*j4+0]);
                    acc[4*j4+1] = fmaf(xi, w.y, acc[4*j4+1]);
                    acc[4*j4+2] = fmaf(xi, w.z, acc[4*j4+2]);
                    acc[4*j4+3] = fmaf(xi, w.w, acc[4*j4+3]);
                }
            }

            #pragma unroll
            for (int j = 0; j < 64; j++) x[j] = fmaxf(acc[j], 0.f);

            if (L == 0) {   // persist o_history for attention aggregate
                float4* Ov = reinterpret_cast<float4*>(g_O + (size_t)p * 64);
                #pragma unroll
                for (int j4 = 0; j4 < 16; j4++)
                    Ov[j4] = make_float4(x[4*j4], x[4*j4+1], x[4*j4+2], x[4*j4+3]);
            }
        }

        // ---- score = x @ a3_W + a3_b ----
        float sc = a3b0;
        #pragma unroll
        for (int j = 0; j < 64; j++) sc = fmaf(x[j], sA3[j], sc);
        g_S[p] = sc;
    }
}

// ---------------------------------------------------------------------------
// Kernel 2: masked softmax over K neighbors + weighted aggregate.
// One warp per node. len==0 -> copy self embedding.
// ---------------------------------------------------------------------------
__global__ void __launch_bounds__(256) k_agg(const int*   __restrict__ nodes,
                                             const int*   __restrict__ nlen,
                                             const float* __restrict__ u2e,
                                             float*       __restrict__ out)
{
    const int wid  = (blockIdx.x * 256 + threadIdx.x) >> 5;
    const int lane = threadIdx.x & 31;
    if (wid >= B_N) return;
    const int b   = wid;
    const int len = nlen[b];

    if (len <= 0) {
        const int node = nodes[b];
        const float2* src = reinterpret_cast<const float2*>(u2e + (size_t)node * 64);
        float2*       dst = reinterpret_cast<float2*>(out + (size_t)b * 64);
        dst[lane] = src[lane];
        return;
    }

    const float* Sb = g_S + (size_t)b * K_N;
    float s0 = (lane      < len) ? Sb[lane]      : -3.0e38f;
    float s1 = (lane + 32 < len) ? Sb[lane + 32] : -3.0e38f;

    float m = fmaxf(s0, s1);
    #pragma unroll
    for (int o = 16; o > 0; o >>= 1) m = fmaxf(m, __shfl_xor_sync(0xffffffffu, m, o));

    const float e0 = (lane      < len) ? expf(s0 - m) : 0.f;
    const float e1 = (lane + 32 < len) ? expf(s1 - m) : 0.f;

    float ss = e0 + e1;
    #pragma unroll
    for (int o = 16; o > 0; o >>= 1) ss += __shfl_xor_sync(0xffffffffu, ss, o);

    const float inv = 1.f / ss;
    const float w0 = e0 * inv;
    const float w1 = e1 * inv;

    float2 agg = make_float2(0.f, 0.f);
    const float2* Ob = reinterpret_cast<const float2*>(g_O + (size_t)b * K_N * 64);
    for (int k = 0; k < len; k++) {
        const float ak = (k < 32) ? __shfl_sync(0xffffffffu, w0, k)
                                  : __shfl_sync(0xffffffffu, w1, k - 32);
        const float2 ov = Ob[k * 32 + lane];
        agg.x = fmaf(ak, ov.x, agg.x);
        agg.y = fmaf(ak, ov.y, agg.y);
    }
    reinterpret_cast<float2*>(out + (size_t)b * 64)[lane] = agg;
}

// ---------------------------------------------------------------------------
// kernel_launch
// ---------------------------------------------------------------------------
extern "C" void kernel_launch(void* const* d_in, const int* in_sizes, int n_in,
                              void* d_out, int out_size)
{
    const int*   nodes  = (const int*)  d_in[0];
    const int*   nidx   = (const int*)  d_in[1];
    const int*   nlen   = (const int*)  d_in[2];
    const float* labels = (const float*)d_in[3];
    const float* u2e    = (const float*)d_in[4];
    const float* w1W    = (const float*)d_in[5];
    const float* w1b    = (const float*)d_in[6];
    const float* w2W    = (const float*)d_in[7];
    const float* w2b    = (const float*)d_in[8];
    const float* a1W    = (const float*)d_in[9];
    const float* a1b    = (const float*)d_in[10];
    const float* a2W    = (const float*)d_in[11];
    const float* a2b    = (const float*)d_in[12];
    const float* a3W    = (const float*)d_in[13];
    const float* a3b    = (const float*)d_in[14];
    float* out = (float*)d_out;

    cudaFuncSetAttribute(k_pairs, cudaFuncAttributeMaxDynamicSharedMemorySize, SMEM_BYTES);

    k_pre  <<<1000, 256>>>(u2e, w1W, a1W);
    k_pairs<<<296, 128, SMEM_BYTES>>>(nodes, nidx, labels,
                                      w1W, w1b, w2W, w2b,
                                      a1W, a1b, a2W, a2b, a3W, a3b);
    k_agg  <<<(B_N * 32 + 255) / 256, 256>>>(nodes, nlen, u2e, out);
}